// round 2
// baseline (speedup 1.0000x reference)
#include <cuda_runtime.h>
#include <cuda_bf16.h>
#include <cstdint>

// Problem constants
#define BB   64      // batch
#define TT   512     // time steps
#define DD   128     // input dim
#define HH   256     // hidden dim
#define G4H  1024    // 4*H

// ---------------------------------------------------------------------------
// Device scratch
// ---------------------------------------------------------------------------
__device__ float g_Gv[(size_t)BB * TT * G4H];
__device__ float g_Gl[(size_t)BB * TT * G4H];
__device__ float g_Gu[(size_t)BB * TT * G4H];
__device__ float4 g_Hvm[2 * BB * HH];   // (v,v,m,m) duplicated, ping-pong
__device__ float2 g_Hrr[2 * BB * HH];   // (r,r) duplicated, ping-pong
__device__ unsigned int g_bar_cnt;

// ---------------------------------------------------------------------------
// f32x2 helpers
// ---------------------------------------------------------------------------
typedef unsigned long long u64;

__device__ __forceinline__ u64 pk(float lo, float hi) {
    u64 r; asm("mov.b64 %0, {%1,%2};" : "=l"(r) : "f"(lo), "f"(hi)); return r;
}
__device__ __forceinline__ void upk(u64 v, float& lo, float& hi) {
    asm("mov.b64 {%0,%1}, %2;" : "=f"(lo), "=f"(hi) : "l"(v));
}
__device__ __forceinline__ u64 fma2(u64 a, u64 b, u64 c) {
    u64 d; asm("fma.rn.f32x2 %0, %1, %2, %3;" : "=l"(d) : "l"(a), "l"(b), "l"(c)); return d;
}

__device__ __forceinline__ float sigf(float x) {
    return __fdividef(1.0f, 1.0f + __expf(-x));
}
__device__ __forceinline__ float tanhf_(float x) {
    return __fdividef(2.0f, 1.0f + __expf(-2.0f * x)) - 1.0f;
}
__device__ __forceinline__ float min4f(float a, float b, float c, float d) {
    return fminf(fminf(a, b), fminf(c, d));
}
__device__ __forceinline__ float max4f(float a, float b, float c, float d) {
    return fmaxf(fmaxf(a, b), fmaxf(c, d));
}

// ---------------------------------------------------------------------------
// Kernel 0: reset grid-barrier counter
// ---------------------------------------------------------------------------
__global__ void bar_reset_kernel() { g_bar_cnt = 0u; }

// ---------------------------------------------------------------------------
// Kernel 1: gx interval GEMM with f32x2.  M=B*T=32768, N=1024, K=128.
// CTA tile 64x64, 256 thr, 4x4 micro (j in f32x2 pairs).
// ---------------------------------------------------------------------------
#define GM 64
#define GN 64
#define GK 16

__global__ __launch_bounds__(256) void gx_gemm_kernel(
    const float* __restrict__ xv, const float* __restrict__ xl,
    const float* __restrict__ xu, const float* __restrict__ W,
    const float* __restrict__ bias)
{
    __shared__ float sAvD[GK][2 * GM + 4];   // duplicated (a,a) pairs
    __shared__ float sAmD[GK][2 * GM + 4];
    __shared__ float sArD[GK][2 * GM + 4];
    __shared__ float sB [GK][GN + 4];
    __shared__ float sBa[GK][GN + 4];

    const int n0 = blockIdx.x * GN;
    const int m0 = blockIdx.y * GM;
    const int tid = threadIdx.x;
    const int tx = tid & 15;
    const int ty = tid >> 4;

    u64 accv[4][2], accm[4][2], accr[4][2];
    const u64 z = pk(0.f, 0.f);
#pragma unroll
    for (int i = 0; i < 4; i++)
#pragma unroll
        for (int j = 0; j < 2; j++) { accv[i][j] = z; accm[i][j] = z; accr[i][j] = z; }

    const int ml = tid >> 2;
    const int kq = tid & 3;

    for (int k0 = 0; k0 < DD; k0 += GK) {
        // stage A (duplicated pairs), transposed to [k][2m]
        {
            const float4 v4 = *(const float4*)(xv + (size_t)(m0 + ml) * DD + k0 + kq * 4);
            const float4 l4 = *(const float4*)(xl + (size_t)(m0 + ml) * DD + k0 + kq * 4);
            const float4 u4 = *(const float4*)(xu + (size_t)(m0 + ml) * DD + k0 + kq * 4);
            const float vv[4] = {v4.x, v4.y, v4.z, v4.w};
            const float ll[4] = {l4.x, l4.y, l4.z, l4.w};
            const float uu[4] = {u4.x, u4.y, u4.z, u4.w};
#pragma unroll
            for (int j = 0; j < 4; j++) {
                const int k = kq * 4 + j;
                const float mu = 0.5f * (ll[j] + uu[j]);
                const float rr = 0.5f * (uu[j] - ll[j]);
                ((float2*)&sAvD[k][0])[ml] = make_float2(vv[j], vv[j]);
                ((float2*)&sAmD[k][0])[ml] = make_float2(mu, mu);
                ((float2*)&sArD[k][0])[ml] = make_float2(rr, rr);
            }
        }
        // stage B and |B|, transposed to [k][n]
        {
            const float4 w4 = *(const float4*)(W + (size_t)(n0 + ml) * DD + k0 + kq * 4);
            const float ww[4] = {w4.x, w4.y, w4.z, w4.w};
#pragma unroll
            for (int j = 0; j < 4; j++) {
                sB [kq * 4 + j][ml] = ww[j];
                sBa[kq * 4 + j][ml] = fabsf(ww[j]);
            }
        }
        __syncthreads();

#pragma unroll
        for (int k = 0; k < GK; k++) {
            const float4 b4  = *(const float4*)&sB [k][tx * 4];
            const float4 ba4 = *(const float4*)&sBa[k][tx * 4];
            const u64 b01 = pk(b4.x, b4.y),  b23 = pk(b4.z, b4.w);
            const u64 a01 = pk(ba4.x, ba4.y), a23 = pk(ba4.z, ba4.w);

            const float4 avA = *(const float4*)&sAvD[k][8 * ty];
            const float4 avB = *(const float4*)&sAvD[k][8 * ty + 4];
            const float4 amA = *(const float4*)&sAmD[k][8 * ty];
            const float4 amB = *(const float4*)&sAmD[k][8 * ty + 4];
            const float4 arA = *(const float4*)&sArD[k][8 * ty];
            const float4 arB = *(const float4*)&sArD[k][8 * ty + 4];

            const u64 avp[4] = {pk(avA.x, avA.y), pk(avA.z, avA.w), pk(avB.x, avB.y), pk(avB.z, avB.w)};
            const u64 amp[4] = {pk(amA.x, amA.y), pk(amA.z, amA.w), pk(amB.x, amB.y), pk(amB.z, amB.w)};
            const u64 arp[4] = {pk(arA.x, arA.y), pk(arA.z, arA.w), pk(arB.x, arB.y), pk(arB.z, arB.w)};

#pragma unroll
            for (int i = 0; i < 4; i++) {
                accv[i][0] = fma2(avp[i], b01, accv[i][0]);
                accv[i][1] = fma2(avp[i], b23, accv[i][1]);
                accm[i][0] = fma2(amp[i], b01, accm[i][0]);
                accm[i][1] = fma2(amp[i], b23, accm[i][1]);
                accr[i][0] = fma2(arp[i], a01, accr[i][0]);
                accr[i][1] = fma2(arp[i], a23, accr[i][1]);
            }
        }
        __syncthreads();
    }

    // epilogue
    float bb4[4];
#pragma unroll
    for (int j = 0; j < 4; j++) bb4[j] = bias[n0 + tx * 4 + j];
#pragma unroll
    for (int i = 0; i < 4; i++) {
        const int m = m0 + ty * 4 + i;
        const size_t o = (size_t)m * G4H + n0 + tx * 4;
        float v0, v1, v2, v3, m0_, m1_, m2_, m3_, r0, r1, r2, r3;
        upk(accv[i][0], v0, v1); upk(accv[i][1], v2, v3);
        upk(accm[i][0], m0_, m1_); upk(accm[i][1], m2_, m3_);
        upk(accr[i][0], r0, r1); upk(accr[i][1], r2, r3);
        const float vv[4] = {v0 + bb4[0], v1 + bb4[1], v2 + bb4[2], v3 + bb4[3]};
        const float mm[4] = {m0_ + bb4[0], m1_ + bb4[1], m2_ + bb4[2], m3_ + bb4[3]};
        const float rr[4] = {r0, r1, r2, r3};
        *(float4*)(g_Gv + o) = make_float4(vv[0], vv[1], vv[2], vv[3]);
        *(float4*)(g_Gl + o) = make_float4(mm[0] - rr[0], mm[1] - rr[1], mm[2] - rr[2], mm[3] - rr[3]);
        *(float4*)(g_Gu + o) = make_float4(mm[0] + rr[0], mm[1] + rr[1], mm[2] + rr[2], mm[3] + rr[3]);
    }
}

// ---------------------------------------------------------------------------
// Kernel 2: persistent recurrent scan (128 CTAs x 128 thr, 1 CTA/SM).
// f32x2 gate-pair packing; h staged in duplicated form; acq/rel grid barrier.
// ---------------------------------------------------------------------------
#define NCTA 128
#define NTHR 128

// smem layout (floats):
//  sW   [0,       8192)   : W  [256 k][8 h][4 g]
//  sWa  [8192,   16384)   : |W|
//  shvm [16384 .. +16448) : [16 b][257 pad] float4 (v,v,m,m)
//  shrr [...    .. +8224) : [16 b][257 pad] float2 (r,r)
#define SM_VM_OFF 16384
#define SM_RR_OFF (16384 + 16 * 257 * 4)
#define SMEM_FLOATS (SM_RR_OFF + 16 * 257 * 2)

__device__ __forceinline__ void grid_barrier(unsigned int target) {
    __syncthreads();
    if (threadIdx.x == 0) {
        asm volatile("red.release.gpu.global.add.u32 [%0], 1;" :: "l"(&g_bar_cnt) : "memory");
        unsigned int v;
        do {
            asm volatile("ld.acquire.gpu.global.u32 %0, [%1];" : "=r"(v) : "l"(&g_bar_cnt) : "memory");
        } while (v < target);
    }
    __syncthreads();
}

__global__ __launch_bounds__(NTHR, 1) void scan_kernel(
    const float* __restrict__ Whh, const float* __restrict__ h0,
    const float* __restrict__ c0, float* __restrict__ out)
{
    extern __shared__ float smem[];
    float*  sW   = smem;
    float*  sWa  = smem + 8192;
    float4* shvm = (float4*)(smem + SM_VM_OFF);
    float2* shrr = (float2*)(smem + SM_RR_OFF);

    const int tid = threadIdx.x;
    const int bc = blockIdx.x & 3;
    const int hc = blockIdx.x >> 2;
    const int b_base = bc * 16;
    const int h_base = hc * 8;
    const int bL = tid >> 3;
    const int hL = tid & 7;
    const int b = b_base + bL;
    const int h = h_base + hL;

    // stage W tile once (sW[k*32 + hh*4 + g])
    for (int idx = tid; idx < 8192; idx += NTHR) {
        const int g  = idx & 3;
        const int hh = (idx >> 2) & 7;
        const int k  = idx >> 5;
        const float w = Whh[(size_t)(g * HH + h_base + hh) * HH + k];
        sW[idx]  = w;
        sWa[idx] = fabsf(w);
    }

    float cv = c0[b * HH + h];
    float cl = cv, cu = cv;

    const float4* wP  = (const float4*)sW  + hL;
    const float4* waP = (const float4*)sWa + hL;
    const float4* hv4 = shvm + bL * 257;
    const float2* hr2 = shrr + bL * 257;

    const u64 z = pk(0.f, 0.f);

    for (int t = 0; t < TT; t++) {
        // prefetch gx for this step (independent of barrier)
        const int gidx = ((b << 9) + t) << 10;
        const float gv0 = __ldcs(g_Gv + gidx + h),       gl0 = __ldcs(g_Gl + gidx + h),       gu0 = __ldcs(g_Gu + gidx + h);
        const float gv1 = __ldcs(g_Gv + gidx + 256 + h), gl1 = __ldcs(g_Gl + gidx + 256 + h), gu1 = __ldcs(g_Gu + gidx + 256 + h);
        const float gv2 = __ldcs(g_Gv + gidx + 512 + h), gl2 = __ldcs(g_Gl + gidx + 512 + h), gu2 = __ldcs(g_Gu + gidx + 512 + h);
        const float gv3 = __ldcs(g_Gv + gidx + 768 + h), gl3 = __ldcs(g_Gl + gidx + 768 + h), gu3 = __ldcs(g_Gu + gidx + 768 + h);

        if (t > 0) grid_barrier((unsigned)t * NCTA);

        // stage previous h (raw copy, duplicated form)
        if (t == 0) {
            for (int idx = tid; idx < 16 * HH; idx += NTHR) {
                const int r = idx >> 8, c = idx & 255;
                const float v = h0[(b_base + r) * HH + c];
                shvm[r * 257 + c] = make_float4(v, v, v, v);
                shrr[r * 257 + c] = make_float2(0.f, 0.f);
            }
        } else {
            const int pp = (t - 1) & 1;
            const float4* srcVM = g_Hvm + pp * (BB * HH);
            const float2* srcRR = g_Hrr + pp * (BB * HH);
            for (int idx = tid; idx < 16 * HH; idx += NTHR) {
                const int r = idx >> 8, c = idx & 255;
                shvm[r * 257 + c] = __ldcg(srcVM + (b_base + r) * HH + c);
                shrr[r * 257 + c] = __ldcg(srcRR + (b_base + r) * HH + c);
            }
        }
        __syncthreads();

        // 12 dot products (f32x2, gate-pair packed)
        u64 av01 = z, av23 = z, am01 = z, am23 = z, ar01 = z, ar23 = z;
#pragma unroll 8
        for (int k = 0; k < HH; k++) {
            const float4 w  = wP [k * 8];
            const float4 wa = waP[k * 8];
            const float4 hq = hv4[k];
            const float2 hr = hr2[k];
            const u64 w01 = pk(w.x, w.y),   w23 = pk(w.z, w.w);
            const u64 q01 = pk(wa.x, wa.y), q23 = pk(wa.z, wa.w);
            const u64 hvv = pk(hq.x, hq.y);
            const u64 hmm = pk(hq.z, hq.w);
            const u64 hrr = pk(hr.x, hr.y);
            av01 = fma2(hvv, w01, av01);
            av23 = fma2(hvv, w23, av23);
            am01 = fma2(hmm, w01, am01);
            am23 = fma2(hmm, w23, am23);
            ar01 = fma2(hrr, q01, ar01);
            ar23 = fma2(hrr, q23, ar23);
        }

        float a_v0, a_v1, a_v2, a_v3, a_m0, a_m1, a_m2, a_m3, a_r0, a_r1, a_r2, a_r3;
        upk(av01, a_v0, a_v1); upk(av23, a_v2, a_v3);
        upk(am01, a_m0, a_m1); upk(am23, a_m2, a_m3);
        upk(ar01, a_r0, a_r1); upk(ar23, a_r2, a_r3);

        const float pv0 = gv0 + a_v0, pl0 = gl0 + a_m0 - a_r0, pu0 = gu0 + a_m0 + a_r0;
        const float pv1 = gv1 + a_v1, pl1 = gl1 + a_m1 - a_r1, pu1 = gu1 + a_m1 + a_r1;
        const float pv2 = gv2 + a_v2, pl2 = gl2 + a_m2 - a_r2, pu2 = gu2 + a_m2 + a_r2;
        const float pv3 = gv3 + a_v3, pl3 = gl3 + a_m3 - a_r3, pu3 = gu3 + a_m3 + a_r3;

        const float iv = sigf(pv0), il = sigf(pl0), iu = sigf(pu0);
        const float fv = sigf(pv1), fl = sigf(pl1), fu = sigf(pu1);
        const float gv = tanhf_(pv2), gl = tanhf_(pl2), gu = tanhf_(pu2);
        const float ov = sigf(pv3), ol = sigf(pl3), ou = sigf(pu3);

        const float t1 = fl * cl, t2 = fl * cu, t3 = fu * cl, t4 = fu * cu;
        const float s1 = il * gl, s2 = il * gu, s3 = iu * gl, s4 = iu * gu;
        cv = fv * cv + iv * gv;
        cl = min4f(t1, t2, t3, t4) + min4f(s1, s2, s3, s4);
        cu = max4f(t1, t2, t3, t4) + max4f(s1, s2, s3, s4);

        const float tv = tanhf_(cv), tl = tanhf_(cl), tu = tanhf_(cu);
        const float u1 = ol * tl, u2 = ol * tu, u3 = ou * tl, u4 = ou * tu;
        const float hn_l = min4f(u1, u2, u3, u4);
        const float hn_u = max4f(u1, u2, u3, u4);
        const float hn_v = ov * tv;

        // store h (duplicated form) for next step
        const int pp2 = t & 1;
        const float hm = 0.5f * (hn_l + hn_u);
        const float hrad = 0.5f * (hn_u - hn_l);
        const int hoff = b * HH + h;
        __stcg(g_Hvm + pp2 * (BB * HH) + hoff, make_float4(hn_v, hn_v, hm, hm));
        __stcg(g_Hrr + pp2 * (BB * HH) + hoff, make_float2(hrad, hrad));

        const size_t obase = ((size_t)(b << 9) + t) * HH + h;
        out[obase] = hn_v;
        out[(size_t)BB * TT * HH + obase] = hn_l;
        out[2 * (size_t)BB * TT * HH + obase] = hn_u;
    }
}

// ---------------------------------------------------------------------------
// Launch
// ---------------------------------------------------------------------------
extern "C" void kernel_launch(void* const* d_in, const int* in_sizes, int n_in,
                              void* d_out, int out_size)
{
    const float* xv   = (const float*)d_in[0];
    const float* xl   = (const float*)d_in[1];
    const float* xu   = (const float*)d_in[2];
    const float* Wih  = (const float*)d_in[3];
    const float* Whh  = (const float*)d_in[4];
    const float* bias = (const float*)d_in[5];
    const float* h0   = (const float*)d_in[6];
    const float* c0   = (const float*)d_in[7];
    float* out = (float*)d_out;

    const int smem_bytes = SMEM_FLOATS * sizeof(float);
    cudaFuncSetAttribute(scan_kernel, cudaFuncAttributeMaxDynamicSharedMemorySize, smem_bytes);

    bar_reset_kernel<<<1, 1>>>();
    gx_gemm_kernel<<<dim3(G4H / GN, (BB * TT) / GM), 256>>>(xv, xl, xu, Wih, bias);
    scan_kernel<<<NCTA, NTHR, smem_bytes>>>(Whh, h0, c0, out);
}

// round 3
// speedup vs baseline: 1.4915x; 1.4915x over previous
#include <cuda_runtime.h>
#include <cuda_bf16.h>
#include <cstdint>

#define BB   64
#define TT   512
#define DD   128
#define HH   256
#define G4H  1024

typedef unsigned long long u64;

// ---------------------------------------------------------------------------
// Device scratch
// ---------------------------------------------------------------------------
__device__ float g_Gv[(size_t)BB * TT * G4H];
__device__ float g_Gl[(size_t)BB * TT * G4H];
__device__ float g_Gu[(size_t)BB * TT * G4H];
__device__ float4 g_Hf4[2 * HH * BB];     // [pp][h-index k][batch] = (v, m, r, _)
__device__ unsigned int g_bar[8];         // per-batch-group barrier counters

// ---------------------------------------------------------------------------
// Helpers
// ---------------------------------------------------------------------------
__device__ __forceinline__ u64 fma2(u64 a, u64 b, u64 c) {
    u64 d; asm("fma.rn.f32x2 %0, %1, %2, %3;" : "=l"(d) : "l"(a), "l"(b), "l"(c)); return d;
}
__device__ __forceinline__ void upk(u64 v, float& lo, float& hi) {
    asm("mov.b64 {%0,%1}, %2;" : "=f"(lo), "=f"(hi) : "l"(v));
}
__device__ __forceinline__ float sigf(float x) {
    return __fdividef(1.0f, 1.0f + __expf(-x));
}
__device__ __forceinline__ float tanhf_(float x) {
    return __fdividef(2.0f, 1.0f + __expf(-2.0f * x)) - 1.0f;
}
__device__ __forceinline__ float min4f(float a, float b, float c, float d) {
    return fminf(fminf(a, b), fminf(c, d));
}
__device__ __forceinline__ float max4f(float a, float b, float c, float d) {
    return fmaxf(fmaxf(a, b), fmaxf(c, d));
}

// ---------------------------------------------------------------------------
// Kernel 1: gx interval GEMM (FFMA2, direct u64 smem loads, zero pk MOVs).
// Also resets the scan's barrier counters (block 0).
// ---------------------------------------------------------------------------
#define GM 64
#define GN 64
#define GK 16

__global__ __launch_bounds__(256) void gx_gemm_kernel(
    const float* __restrict__ xv, const float* __restrict__ xl,
    const float* __restrict__ xu, const float* __restrict__ W,
    const float* __restrict__ bias)
{
    if (blockIdx.x == 0 && blockIdx.y == 0 && threadIdx.x < 8)
        g_bar[threadIdx.x] = 0u;

    __shared__ float sAvD[GK][2 * GM + 4];   // duplicated (a,a) pairs
    __shared__ float sAmD[GK][2 * GM + 4];
    __shared__ float sArD[GK][2 * GM + 4];
    __shared__ float sB [GK][GN + 4];
    __shared__ float sBa[GK][GN + 4];

    const int n0 = blockIdx.x * GN;
    const int m0 = blockIdx.y * GM;
    const int tid = threadIdx.x;
    const int tx = tid & 15;
    const int ty = tid >> 4;

    u64 accv[4][2], accm[4][2], accr[4][2];
#pragma unroll
    for (int i = 0; i < 4; i++)
#pragma unroll
        for (int j = 0; j < 2; j++) { accv[i][j] = 0ull; accm[i][j] = 0ull; accr[i][j] = 0ull; }

    const int ml = tid >> 2;
    const int kq = tid & 3;

    for (int k0 = 0; k0 < DD; k0 += GK) {
        {
            const float4 v4 = *(const float4*)(xv + (size_t)(m0 + ml) * DD + k0 + kq * 4);
            const float4 l4 = *(const float4*)(xl + (size_t)(m0 + ml) * DD + k0 + kq * 4);
            const float4 u4 = *(const float4*)(xu + (size_t)(m0 + ml) * DD + k0 + kq * 4);
            const float vv[4] = {v4.x, v4.y, v4.z, v4.w};
            const float ll[4] = {l4.x, l4.y, l4.z, l4.w};
            const float uu[4] = {u4.x, u4.y, u4.z, u4.w};
#pragma unroll
            for (int j = 0; j < 4; j++) {
                const int k = kq * 4 + j;
                const float mu = 0.5f * (ll[j] + uu[j]);
                const float rr = 0.5f * (uu[j] - ll[j]);
                ((float2*)&sAvD[k][0])[ml] = make_float2(vv[j], vv[j]);
                ((float2*)&sAmD[k][0])[ml] = make_float2(mu, mu);
                ((float2*)&sArD[k][0])[ml] = make_float2(rr, rr);
            }
        }
        {
            const float4 w4 = *(const float4*)(W + (size_t)(n0 + ml) * DD + k0 + kq * 4);
            const float ww[4] = {w4.x, w4.y, w4.z, w4.w};
#pragma unroll
            for (int j = 0; j < 4; j++) {
                sB [kq * 4 + j][ml] = ww[j];
                sBa[kq * 4 + j][ml] = fabsf(ww[j]);
            }
        }
        __syncthreads();

#pragma unroll
        for (int k = 0; k < GK; k++) {
            const u64 b01 = *(const u64*)&sB [k][tx * 4];
            const u64 b23 = *(const u64*)&sB [k][tx * 4 + 2];
            const u64 a01 = *(const u64*)&sBa[k][tx * 4];
            const u64 a23 = *(const u64*)&sBa[k][tx * 4 + 2];
#pragma unroll
            for (int i = 0; i < 4; i++) {
                const u64 av = *(const u64*)&sAvD[k][2 * (4 * ty + i)];
                const u64 am = *(const u64*)&sAmD[k][2 * (4 * ty + i)];
                const u64 ar = *(const u64*)&sArD[k][2 * (4 * ty + i)];
                accv[i][0] = fma2(av, b01, accv[i][0]);
                accv[i][1] = fma2(av, b23, accv[i][1]);
                accm[i][0] = fma2(am, b01, accm[i][0]);
                accm[i][1] = fma2(am, b23, accm[i][1]);
                accr[i][0] = fma2(ar, a01, accr[i][0]);
                accr[i][1] = fma2(ar, a23, accr[i][1]);
            }
        }
        __syncthreads();
    }

    float bb4[4];
#pragma unroll
    for (int j = 0; j < 4; j++) bb4[j] = bias[n0 + tx * 4 + j];
#pragma unroll
    for (int i = 0; i < 4; i++) {
        const int m = m0 + ty * 4 + i;
        const size_t o = (size_t)m * G4H + n0 + tx * 4;
        float v0, v1, v2, v3, q0, q1, q2, q3, r0, r1, r2, r3;
        upk(accv[i][0], v0, v1); upk(accv[i][1], v2, v3);
        upk(accm[i][0], q0, q1); upk(accm[i][1], q2, q3);
        upk(accr[i][0], r0, r1); upk(accr[i][1], r2, r3);
        *(float4*)(g_Gv + o) = make_float4(v0 + bb4[0], v1 + bb4[1], v2 + bb4[2], v3 + bb4[3]);
        *(float4*)(g_Gl + o) = make_float4(q0 + bb4[0] - r0, q1 + bb4[1] - r1, q2 + bb4[2] - r2, q3 + bb4[3] - r3);
        *(float4*)(g_Gu + o) = make_float4(q0 + bb4[0] + r0, q1 + bb4[1] + r1, q2 + bb4[2] + r2, q3 + bb4[3] + r3);
    }
}

// ---------------------------------------------------------------------------
// Kernel 2: persistent scan.  128 CTAs x 256 thr (1/SM, 2 warps/SMSP).
// CTA owns 8 batches x 16 h; each cell split across 2 threads (k halves).
// 8 independent batch-groups (16 CTAs each) with per-group barriers.
// ---------------------------------------------------------------------------
#define NCTA 128
#define NTHR 256

// smem (floats):
//  sW   [0,      16384) : [256 k][16 h][4 g]
//  sWa  [16384,  32768) : |W|
//  sH   [32768,  40960) : float4 [256 k][8 b] = (v, m, r, _)
//  sRed [40960,  42624) : [128][13]
#define SMEM_FLOATS 42624

__global__ __launch_bounds__(NTHR, 1) void scan_kernel(
    const float* __restrict__ Whh, const float* __restrict__ h0,
    const float* __restrict__ c0, float* __restrict__ out)
{
    extern __shared__ float smem[];
    float*  sW   = smem;
    float*  sWa  = smem + 16384;
    float4* sH   = (float4*)(smem + 32768);
    float*  sRed = smem + 40960;

    const int tid = threadIdx.x;
    const int gb = blockIdx.x >> 4;      // batch group 0..7
    const int hc = blockIdx.x & 15;      // h chunk 0..15
    const int c  = tid & 127;            // cell id in CTA
    const int khalf = tid >> 7;          // 0: k<128, 1: k>=128
    const int bL = c & 7;
    const int hL = c >> 3;               // 0..15
    const int b  = gb * 8 + bL;
    const int hg = hc * 16 + hL;

    // stage W (+|W|) once: sW[k*64 + hh*4 + g]
    for (int idx = tid; idx < 16384; idx += NTHR) {
        const int g  = idx & 3;
        const int hh = (idx >> 2) & 15;
        const int k  = idx >> 6;
        const float w = Whh[(size_t)(g * HH + hc * 16 + hh) * HH + k];
        sW[idx]  = w;
        sWa[idx] = fabsf(w);
    }

    float cv = 0.f, cl = 0.f, cu = 0.f;
    if (khalf == 0) { cv = c0[b * HH + hg]; cl = cv; cu = cv; }

    const int kbase = khalf * 128;
    unsigned int* barp = &g_bar[gb];
    const float4* wp = (const float4*)sW;
    const float4* qp = (const float4*)sWa;

    for (int t = 0; t < TT; t++) {
        // gx prefetch (before barrier; khalf is warp-uniform)
        float gv0, gl0, gu0, gv1, gl1, gu1, gv2, gl2, gu2, gv3, gl3, gu3;
        if (khalf == 0) {
            const int gidx = ((b << 9) + t) << 10;
            gv0 = __ldcs(g_Gv + gidx + hg);       gl0 = __ldcs(g_Gl + gidx + hg);       gu0 = __ldcs(g_Gu + gidx + hg);
            gv1 = __ldcs(g_Gv + gidx + 256 + hg); gl1 = __ldcs(g_Gl + gidx + 256 + hg); gu1 = __ldcs(g_Gu + gidx + 256 + hg);
            gv2 = __ldcs(g_Gv + gidx + 512 + hg); gl2 = __ldcs(g_Gl + gidx + 512 + hg); gu2 = __ldcs(g_Gu + gidx + 512 + hg);
            gv3 = __ldcs(g_Gv + gidx + 768 + hg); gl3 = __ldcs(g_Gl + gidx + 768 + hg); gu3 = __ldcs(g_Gu + gidx + 768 + hg);
        }

        if (t > 0) {
            __syncthreads();
            if (tid == 0) {
                asm volatile("red.release.gpu.global.add.u32 [%0], 1;" :: "l"(barp) : "memory");
                unsigned int v;
                do {
                    asm volatile("ld.acquire.gpu.global.u32 %0, [%1];" : "=r"(v) : "l"(barp) : "memory");
                } while (v < (unsigned)t * 16u);
            }
            __syncthreads();
        }

        // stage previous h: sH[k*8 + b] = (v, m, r, _)
        if (t == 0) {
            for (int idx = tid; idx < 2048; idx += NTHR) {
                const int k = idx >> 3, bb = idx & 7;
                const float v = h0[(gb * 8 + bb) * HH + k];
                sH[idx] = make_float4(v, v, 0.f, 0.f);
            }
        } else {
            const float4* src = g_Hf4 + ((t - 1) & 1) * (HH * BB) + gb * 8;
            for (int idx = tid; idx < 2048; idx += NTHR) {
                const int k = idx >> 3, bb = idx & 7;
                sH[idx] = __ldcg(src + k * BB + bb);
            }
        }
        __syncthreads();

        // half k-loop: 128 iters, 3x LDS.128 + 12 FFMA per iter
        float av0 = 0.f, av1 = 0.f, av2 = 0.f, av3 = 0.f;
        float am0 = 0.f, am1 = 0.f, am2 = 0.f, am3 = 0.f;
        float ar0 = 0.f, ar1 = 0.f, ar2 = 0.f, ar3 = 0.f;
#pragma unroll 8
        for (int k = kbase; k < kbase + 128; k++) {
            const float4 w  = wp[k * 16 + hL];
            const float4 q  = qp[k * 16 + hL];
            const float4 h4 = sH[k * 8 + bL];
            av0 = fmaf(h4.x, w.x, av0); av1 = fmaf(h4.x, w.y, av1);
            av2 = fmaf(h4.x, w.z, av2); av3 = fmaf(h4.x, w.w, av3);
            am0 = fmaf(h4.y, w.x, am0); am1 = fmaf(h4.y, w.y, am1);
            am2 = fmaf(h4.y, w.z, am2); am3 = fmaf(h4.y, w.w, am3);
            ar0 = fmaf(h4.z, q.x, ar0); ar1 = fmaf(h4.z, q.y, ar1);
            ar2 = fmaf(h4.z, q.z, ar2); ar3 = fmaf(h4.z, q.w, ar3);
        }

        // combine k-halves
        if (khalf == 1) {
            float* r = sRed + c * 13;
            r[0] = av0; r[1] = av1; r[2]  = av2; r[3]  = av3;
            r[4] = am0; r[5] = am1; r[6]  = am2; r[7]  = am3;
            r[8] = ar0; r[9] = ar1; r[10] = ar2; r[11] = ar3;
        }
        __syncthreads();

        if (khalf == 0) {
            const float* r = sRed + c * 13;
            av0 += r[0]; av1 += r[1]; av2 += r[2];  av3 += r[3];
            am0 += r[4]; am1 += r[5]; am2 += r[6];  am3 += r[7];
            ar0 += r[8]; ar1 += r[9]; ar2 += r[10]; ar3 += r[11];

            const float pv0 = gv0 + av0, pl0 = gl0 + am0 - ar0, pu0 = gu0 + am0 + ar0;
            const float pv1 = gv1 + av1, pl1 = gl1 + am1 - ar1, pu1 = gu1 + am1 + ar1;
            const float pv2 = gv2 + av2, pl2 = gl2 + am2 - ar2, pu2 = gu2 + am2 + ar2;
            const float pv3 = gv3 + av3, pl3 = gl3 + am3 - ar3, pu3 = gu3 + am3 + ar3;

            const float iv = sigf(pv0), il = sigf(pl0), iu = sigf(pu0);
            const float fv = sigf(pv1), fl = sigf(pl1), fu = sigf(pu1);
            const float gv = tanhf_(pv2), gl = tanhf_(pl2), gu = tanhf_(pu2);
            const float ov = sigf(pv3), ol = sigf(pl3), ou = sigf(pu3);

            const float t1 = fl * cl, t2 = fl * cu, t3 = fu * cl, t4 = fu * cu;
            const float s1 = il * gl, s2 = il * gu, s3 = iu * gl, s4 = iu * gu;
            cv = fv * cv + iv * gv;
            cl = min4f(t1, t2, t3, t4) + min4f(s1, s2, s3, s4);
            cu = max4f(t1, t2, t3, t4) + max4f(s1, s2, s3, s4);

            const float tv = tanhf_(cv), tl = tanhf_(cl), tu = tanhf_(cu);
            const float u1 = ol * tl, u2 = ol * tu, u3 = ou * tl, u4 = ou * tu;
            const float hn_l = min4f(u1, u2, u3, u4);
            const float hn_u = max4f(u1, u2, u3, u4);
            const float hn_v = ov * tv;

            // publish h (transposed [h][b]) for next step
            const float hm = 0.5f * (hn_l + hn_u);
            const float hr = 0.5f * (hn_u - hn_l);
            __stcg(g_Hf4 + (t & 1) * (HH * BB) + hg * BB + b,
                   make_float4(hn_v, hm, hr, 0.f));

            const size_t obase = ((size_t)(b << 9) + t) * HH + hg;
            out[obase] = hn_v;
            out[(size_t)BB * TT * HH + obase] = hn_l;
            out[2 * (size_t)BB * TT * HH + obase] = hn_u;
        }
    }
}

// ---------------------------------------------------------------------------
// Launch
// ---------------------------------------------------------------------------
extern "C" void kernel_launch(void* const* d_in, const int* in_sizes, int n_in,
                              void* d_out, int out_size)
{
    const float* xv   = (const float*)d_in[0];
    const float* xl   = (const float*)d_in[1];
    const float* xu   = (const float*)d_in[2];
    const float* Wih  = (const float*)d_in[3];
    const float* Whh  = (const float*)d_in[4];
    const float* bias = (const float*)d_in[5];
    const float* h0   = (const float*)d_in[6];
    const float* c0   = (const float*)d_in[7];
    float* out = (float*)d_out;

    const int smem_bytes = SMEM_FLOATS * sizeof(float);   // ~166 KB
    cudaFuncSetAttribute(scan_kernel, cudaFuncAttributeMaxDynamicSharedMemorySize, smem_bytes);

    gx_gemm_kernel<<<dim3(G4H / GN, (BB * TT) / GM), 256>>>(xv, xl, xu, Wih, bias);
    scan_kernel<<<NCTA, NTHR, smem_bytes>>>(Whh, h0, c0, out);
}